// round 7
// baseline (speedup 1.0000x reference)
#include <cuda_runtime.h>
#include <cuda_fp16.h>
#include <cstdint>

// ---------------------------------------------------------------------------
// out[i] = sum_{e: w_rows[e]==i} Param_W[w_params[e]] * x[w_cols[e]]
//          + Param_b[b_params[i]]
//
// N = 262144, E = 16.7M. Edge kernel is jointly bound: L2 bytes (REDs 1.07GB +
// gather misses 0.42GB + streams 0.2GB ~= LTS cap) and L1tex wavefronts.
// R6: (1) x cached as fp16 in __device__ scratch -> 512KB footprint doubles
//     the L1 hit rate on gathers, cutting the L2 gather-miss term ~30%.
// (2) Param_W gathers moved to smem -> removes ~30% of L1tex wavefronts.
// Products stay fp32; fp16 only quantizes x (<=4.9e-4/term, ~6e-5 norm-wise).
// ---------------------------------------------------------------------------

#define NMAX        262144
#define NPARAMS_MAX 2048

__device__ __half g_x16[NMAX];   // fp16 copy of x (allowed: __device__ global)

// Prologue: convert x -> fp16 scratch AND write the gathered bias into out
// (also clears the 0xAA poison). One launch, trivially memory-light (2.5MB).
__global__ void prologue_kernel(const float* __restrict__ x,
                                const float* __restrict__ Param_b,
                                const int4*  __restrict__ b_params4,
                                float4*      __restrict__ out4,
                                int N4, int N)
{
    int i = blockIdx.x * blockDim.x + threadIdx.x;
    if (i < N4) {
        int base = i * 4;
        float4 xv = ((const float4*)x)[i];
        g_x16[base + 0] = __float2half(xv.x);
        g_x16[base + 1] = __float2half(xv.y);
        g_x16[base + 2] = __float2half(xv.z);
        g_x16[base + 3] = __float2half(xv.w);

        int4 b = b_params4[i];
        float4 o;
        o.x = __ldg(&Param_b[b.x]);
        o.y = __ldg(&Param_b[b.y]);
        o.z = __ldg(&Param_b[b.z]);
        o.w = __ldg(&Param_b[b.w]);
        out4[i] = o;
    }
}

__global__ void prologue_tail_kernel(const float* __restrict__ x,
                                     const float* __restrict__ Param_b,
                                     const int*   __restrict__ b_params,
                                     float*       __restrict__ out,
                                     int start, int N)
{
    int i = start + blockIdx.x * blockDim.x + threadIdx.x;
    if (i < N) {
        g_x16[i] = __float2half(x[i]);
        out[i]   = __ldg(&Param_b[b_params[i]]);
    }
}

// Edge scatter: 4 edges/thread (proven shape). x gathers from fp16 scratch,
// Param_W from smem, streams evict-first, REDs to L2.
__global__ void __launch_bounds__(256)
edge_scatter_f16_kernel(const float* __restrict__ Param_W,
                        const int4*  __restrict__ rows4,
                        const int4*  __restrict__ cols4,
                        const int4*  __restrict__ params4,
                        float*       __restrict__ out,
                        int E4, int nparams)
{
    __shared__ float sPW[NPARAMS_MAX];
    for (int i = threadIdx.x; i < nparams; i += blockDim.x)
        sPW[i] = Param_W[i];
    __syncthreads();

    int t = blockIdx.x * blockDim.x + threadIdx.x;
    if (t >= E4) return;

    int4 r = __ldcs(&rows4[t]);
    int4 c = __ldcs(&cols4[t]);
    int4 p = __ldcs(&params4[t]);

    // fp16 x gathers (512KB footprint -> ~2x L1 hit rate vs fp32).
    float x0 = __half2float(g_x16[c.x]);
    float x1 = __half2float(g_x16[c.y]);
    float x2 = __half2float(g_x16[c.z]);
    float x3 = __half2float(g_x16[c.w]);

    float v0 = sPW[p.x] * x0;
    float v1 = sPW[p.y] * x1;
    float v2 = sPW[p.z] * x2;
    float v3 = sPW[p.w] * x3;

    atomicAdd(&out[r.x], v0);
    atomicAdd(&out[r.y], v1);
    atomicAdd(&out[r.z], v2);
    atomicAdd(&out[r.w], v3);
}

__global__ void edge_scatter_tail_kernel(const float* __restrict__ x,
                                         const float* __restrict__ Param_W,
                                         const int*   __restrict__ rows,
                                         const int*   __restrict__ cols,
                                         const int*   __restrict__ params,
                                         float*       __restrict__ out,
                                         int start, int E)
{
    int e = start + blockIdx.x * blockDim.x + threadIdx.x;
    if (e < E) {
        float v = __ldg(&Param_W[params[e]]) * __ldg(&x[cols[e]]);
        atomicAdd(&out[rows[e]], v);
    }
}

extern "C" void kernel_launch(void* const* d_in, const int* in_sizes, int n_in,
                              void* d_out, int out_size)
{
    const float* x        = (const float*)d_in[0];
    const float* Param_W  = (const float*)d_in[1];
    const float* Param_b  = (const float*)d_in[2];
    const int*   w_rows   = (const int*)  d_in[3];
    const int*   w_cols   = (const int*)  d_in[4];
    const int*   w_params = (const int*)  d_in[5];
    const int*   b_params = (const int*)  d_in[6];
    float*       out      = (float*)d_out;

    const int N       = out_size;     // 262144 (must be <= NMAX for f16 path)
    const int E       = in_sizes[3];  // 16777216
    const int nparams = in_sizes[1] < NPARAMS_MAX ? in_sizes[1] : NPARAMS_MAX;

    // 1) Prologue: x -> fp16 scratch, out = gathered bias.
    {
        int N4 = N / 4;
        if (N4 > 0) {
            int threads = 256;
            int blocks  = (N4 + threads - 1) / threads;
            prologue_kernel<<<blocks, threads>>>(
                x, Param_b, (const int4*)b_params, (float4*)out, N4, N);
        }
        int rem = N4 * 4;
        if (N - rem > 0) {
            prologue_tail_kernel<<<1, 256>>>(x, Param_b, b_params, out, rem, N);
        }
    }

    // 2) Edge scatter from fp16 x + smem Param_W.
    {
        int E4 = E / 4;
        if (E4 > 0 && N <= NMAX) {
            int threads = 256;
            int blocks  = (E4 + threads - 1) / threads;
            edge_scatter_f16_kernel<<<blocks, threads>>>(
                Param_W,
                (const int4*)w_rows, (const int4*)w_cols, (const int4*)w_params,
                out, E4, nparams);
        } else if (E4 > 0) {
            // Safety fallback (shape mismatch): fp32 direct path.
            edge_scatter_tail_kernel<<<(E + 255) / 256, 256>>>(
                x, Param_W, w_rows, w_cols, w_params, out, 0, E);
            return;
        }
        int tail_start = E4 * 4;
        if (E - tail_start > 0) {
            edge_scatter_tail_kernel<<<1, 256>>>(
                x, Param_W, w_rows, w_cols, w_params, out, tail_start, E);
        }
    }
}

// round 8
// speedup vs baseline: 1.0730x; 1.0730x over previous
#include <cuda_runtime.h>
#include <cuda_fp16.h>
#include <cstdint>

// ---------------------------------------------------------------------------
// out[i] = sum_{e: w_rows[e]==i} Param_W[w_params[e]] * x[w_cols[e]]
//          + Param_b[b_params[i]]
//
// N = 262144, E = 16.7M. Binding resource: LTS bytes (REDs 1.07GB fixed +
// gather misses + streams). R7 = R5 fused structure + fp16 x scratch only:
// halved gather footprint (512KB) doubles L1 residency -> ~30% fewer
// gather-miss L2 bytes. Param_W via __ldg (smem variant proven regressive
// in R3/R6: random-LDS bank conflicts + 84MB staging traffic).
// ---------------------------------------------------------------------------

#define NMAX 262144

__device__ __half g_x16[NMAX];   // fp16 copy of x (__device__ global scratch)

// Prologue: x -> fp16 scratch, out = gathered bias (clears poison).
__global__ void prologue_kernel(const float* __restrict__ x,
                                const float* __restrict__ Param_b,
                                const int4*  __restrict__ b_params4,
                                float4*      __restrict__ out4,
                                int N4)
{
    int i = blockIdx.x * blockDim.x + threadIdx.x;
    if (i < N4) {
        float4 xv = ((const float4*)x)[i];
        __half2* dst = (__half2*)&g_x16[i * 4];
        dst[0] = __floats2half2_rn(xv.x, xv.y);
        dst[1] = __floats2half2_rn(xv.z, xv.w);

        int4 b = b_params4[i];
        float4 o;
        o.x = __ldg(&Param_b[b.x]);
        o.y = __ldg(&Param_b[b.y]);
        o.z = __ldg(&Param_b[b.z]);
        o.w = __ldg(&Param_b[b.w]);
        out4[i] = o;
    }
}

__global__ void prologue_tail_kernel(const float* __restrict__ x,
                                     const float* __restrict__ Param_b,
                                     const int*   __restrict__ b_params,
                                     float*       __restrict__ out,
                                     int start, int N)
{
    int i = start + blockIdx.x * blockDim.x + threadIdx.x;
    if (i < N) {
        g_x16[i] = __float2half(x[i]);
        out[i]   = __ldg(&Param_b[b_params[i]]);
    }
}

// Edge scatter: 4 edges/thread, R1-proven shape; only the x source differs.
__global__ void __launch_bounds__(256)
edge_scatter_f16_kernel(const float* __restrict__ Param_W,
                        const int4*  __restrict__ rows4,
                        const int4*  __restrict__ cols4,
                        const int4*  __restrict__ params4,
                        float*       __restrict__ out,
                        int E4)
{
    int t = blockIdx.x * blockDim.x + threadIdx.x;
    if (t >= E4) return;

    int4 r = __ldcs(&rows4[t]);
    int4 c = __ldcs(&cols4[t]);
    int4 p = __ldcs(&params4[t]);

    // fp16 x gathers: 512KB footprint, ~44% L1-resident.
    float x0 = __half2float(g_x16[c.x]);
    float x1 = __half2float(g_x16[c.y]);
    float x2 = __half2float(g_x16[c.z]);
    float x3 = __half2float(g_x16[c.w]);

    // Param_W: 5KB, L1-hot via __ldg (NOT smem — see header note).
    float v0 = __ldg(&Param_W[p.x]) * x0;
    float v1 = __ldg(&Param_W[p.y]) * x1;
    float v2 = __ldg(&Param_W[p.z]) * x2;
    float v3 = __ldg(&Param_W[p.w]) * x3;

    atomicAdd(&out[r.x], v0);
    atomicAdd(&out[r.y], v1);
    atomicAdd(&out[r.z], v2);
    atomicAdd(&out[r.w], v3);
}

__global__ void edge_scatter_tail_kernel(const float* __restrict__ x,
                                         const float* __restrict__ Param_W,
                                         const int*   __restrict__ rows,
                                         const int*   __restrict__ cols,
                                         const int*   __restrict__ params,
                                         float*       __restrict__ out,
                                         int start, int E)
{
    int e = start + blockIdx.x * blockDim.x + threadIdx.x;
    if (e < E) {
        float v = __ldg(&Param_W[params[e]]) * __ldg(&x[cols[e]]);
        atomicAdd(&out[rows[e]], v);
    }
}

// Full-fp32 fallback for unexpected shapes (N > NMAX).
__global__ void __launch_bounds__(256)
edge_scatter_f32_kernel(const float* __restrict__ x,
                        const float* __restrict__ Param_W,
                        const int4*  __restrict__ rows4,
                        const int4*  __restrict__ cols4,
                        const int4*  __restrict__ params4,
                        float*       __restrict__ out,
                        int E4)
{
    int t = blockIdx.x * blockDim.x + threadIdx.x;
    if (t >= E4) return;
    int4 r = __ldcs(&rows4[t]);
    int4 c = __ldcs(&cols4[t]);
    int4 p = __ldcs(&params4[t]);
    float v0 = __ldg(&Param_W[p.x]) * __ldg(&x[c.x]);
    float v1 = __ldg(&Param_W[p.y]) * __ldg(&x[c.y]);
    float v2 = __ldg(&Param_W[p.z]) * __ldg(&x[c.z]);
    float v3 = __ldg(&Param_W[p.w]) * __ldg(&x[c.w]);
    atomicAdd(&out[r.x], v0);
    atomicAdd(&out[r.y], v1);
    atomicAdd(&out[r.z], v2);
    atomicAdd(&out[r.w], v3);
}

__global__ void bias_only_kernel(const float* __restrict__ Param_b,
                                 const int*   __restrict__ b_params,
                                 float*       __restrict__ out, int N)
{
    int i = blockIdx.x * blockDim.x + threadIdx.x;
    if (i < N) out[i] = __ldg(&Param_b[b_params[i]]);
}

extern "C" void kernel_launch(void* const* d_in, const int* in_sizes, int n_in,
                              void* d_out, int out_size)
{
    const float* x        = (const float*)d_in[0];
    const float* Param_W  = (const float*)d_in[1];
    const float* Param_b  = (const float*)d_in[2];
    const int*   w_rows   = (const int*)  d_in[3];
    const int*   w_cols   = (const int*)  d_in[4];
    const int*   w_params = (const int*)  d_in[5];
    const int*   b_params = (const int*)  d_in[6];
    float*       out      = (float*)d_out;

    const int N = out_size;       // 262144
    const int E = in_sizes[3];    // 16777216
    int E4 = E / 4;

    if (N <= NMAX) {
        // 1) Prologue: fp16 conversion + bias init, one light launch.
        int N4 = N / 4;
        if (N4 > 0) {
            int threads = 256;
            int blocks  = (N4 + threads - 1) / threads;
            prologue_kernel<<<blocks, threads>>>(
                x, Param_b, (const int4*)b_params, (float4*)out, N4);
        }
        int rem = N4 * 4;
        if (N - rem > 0) {
            prologue_tail_kernel<<<1, 256>>>(x, Param_b, b_params, out, rem, N);
        }

        // 2) Edge scatter from fp16 x.
        if (E4 > 0) {
            int threads = 256;
            int blocks  = (E4 + threads - 1) / threads;
            edge_scatter_f16_kernel<<<blocks, threads>>>(
                Param_W,
                (const int4*)w_rows, (const int4*)w_cols, (const int4*)w_params,
                out, E4);
        }
    } else {
        // Fallback: fp32 path for oversized N.
        bias_only_kernel<<<(N + 255) / 256, 256>>>(Param_b, b_params, out, N);
        if (E4 > 0) {
            int threads = 256;
            int blocks  = (E4 + threads - 1) / threads;
            edge_scatter_f32_kernel<<<blocks, threads>>>(
                x, Param_W,
                (const int4*)w_rows, (const int4*)w_cols, (const int4*)w_params,
                out, E4);
        }
    }

    int tail_start = E4 * 4;
    if (E - tail_start > 0) {
        edge_scatter_tail_kernel<<<1, 256>>>(
            x, Param_W, w_rows, w_cols, w_params, out, tail_start, E);
    }
}